// round 13
// baseline (speedup 1.0000x reference)
#include <cuda_runtime.h>
#include <cuda_fp16.h>
#include <cstdint>

#define DIM 2048
#define HID 1024
#define NEXP 8
#define TOTAL 16384

// fp16 copies of inputs (converted once per launch) + fp16 h buffer
__device__ __half g_x16[(size_t)TOTAL * DIM];
__device__ __half g_g16[(size_t)NEXP * HID * DIM];
__device__ __half g_u16[(size_t)NEXP * HID * DIM];
__device__ __half g_d16[(size_t)NEXP * DIM * HID];
__device__ __half g_h16[(size_t)TOTAL * HID];

__device__ __forceinline__ uint32_t smem_u32(const void* p) {
    uint32_t a;
    asm("{ .reg .u64 t; cvta.to.shared.u64 t, %1; cvt.u32.u64 %0, t; }" : "=r"(a) : "l"(p));
    return a;
}
__device__ __forceinline__ void ldsm4(uint32_t r[4], uint32_t addr) {
    asm volatile("ldmatrix.sync.aligned.m8n8.x4.shared.b16 {%0,%1,%2,%3}, [%4];"
                 : "=r"(r[0]), "=r"(r[1]), "=r"(r[2]), "=r"(r[3]) : "r"(addr));
}
__device__ __forceinline__ void mma16816(float c[4], const uint32_t a[4], const uint32_t b[2]) {
    asm volatile(
        "mma.sync.aligned.m16n8k16.row.col.f32.f16.f16.f32 "
        "{%0,%1,%2,%3}, {%4,%5,%6,%7}, {%8,%9}, {%0,%1,%2,%3};"
        : "+f"(c[0]), "+f"(c[1]), "+f"(c[2]), "+f"(c[3])
        : "r"(a[0]), "r"(a[1]), "r"(a[2]), "r"(a[3]), "r"(b[0]), "r"(b[1]));
}
__device__ __forceinline__ void cpa16(uint32_t dst, const void* src) {
    asm volatile("cp.async.cg.shared.global [%0], [%1], 16;" :: "r"(dst), "l"(src) : "memory");
}
#define CP_COMMIT() asm volatile("cp.async.commit_group;" ::: "memory")
#define CP_WAIT0()  asm volatile("cp.async.wait_group 0;" ::: "memory")

// 64-col sub-tile: rows are 128 bytes; chunk = 16B unit, XOR-8 swizzle (verified).
__device__ __forceinline__ uint32_t tile_addr(uint32_t base, int row, int chunk) {
    return base + row * 128 + (((chunk ^ (row & 7)) & 7) << 4);
}

__device__ __forceinline__ void cvt8(const float* __restrict__ s, __half* __restrict__ d, size_t i) {
    const float4* sp = reinterpret_cast<const float4*>(s) + i * 2;
    float4 a = __ldcs(sp);
    float4 b = __ldcs(sp + 1);
    __half2 h0 = __float22half2_rn(make_float2(a.x, a.y));
    __half2 h1 = __float22half2_rn(make_float2(a.z, a.w));
    __half2 h2 = __float22half2_rn(make_float2(b.x, b.y));
    __half2 h3 = __float22half2_rn(make_float2(b.z, b.w));
    uint4 o = make_uint4(*reinterpret_cast<uint32_t*>(&h0), *reinterpret_cast<uint32_t*>(&h1),
                         *reinterpret_cast<uint32_t*>(&h2), *reinterpret_cast<uint32_t*>(&h3));
    reinterpret_cast<uint4*>(d)[i] = o;
}

#define NX8 ((size_t)TOTAL * DIM / 8)
#define NW8 ((size_t)NEXP * HID * DIM / 8)
__global__ __launch_bounds__(256) void cvt3_kernel(const float* __restrict__ x,
                                                   const float* __restrict__ g,
                                                   const float* __restrict__ u)
{
    const size_t n = NX8 + 2 * NW8;
    size_t idx = (size_t)blockIdx.x * blockDim.x + threadIdx.x;
    size_t stride = (size_t)gridDim.x * blockDim.x;
    for (size_t i = idx; i < n; i += stride) {
        if (i < NX8)            cvt8(x, g_x16, i);
        else if (i < NX8 + NW8) cvt8(g, g_g16, i - NX8);
        else                    cvt8(u, g_u16, i - NX8 - NW8);
    }
}

__global__ __launch_bounds__(256) void cvt_kernel(const float* __restrict__ src,
                                                  __half* __restrict__ dst, size_t n8)
{
    size_t idx = (size_t)blockIdx.x * blockDim.x + threadIdx.x;
    size_t stride = (size_t)gridDim.x * blockDim.x;
    for (size_t i = idx; i < n8; i += stride) cvt8(src, dst, i);
}

// ---------------------------------------------------------------------------
// Kernel 1: gateup, persistent. CTA tile BM=256 x (64 gate + 64 up), BK=128.
// 8 warps (4M x 2N), warp tile 64x32 per matrix. Tiles: 16 x 64 = 1024, NK=16.
// 2 stages x 96K = 192K smem. Double-buffer: WAIT0 -> SYNC -> (issue it+1
// spread 3-per-q) -> compute it. One commit per iteration (tail-safe).
// Stage layout: A[2 kblk x 256r x 128B]=64K, G[2 x 64 x 128B]=16K, U=16K.
// ---------------------------------------------------------------------------
#define GU_STAGE_B 98304
#define GU_NT 1024
#define GU_NK 16
__global__ __launch_bounds__(256, 1) void gateup_kernel(const int* __restrict__ counts)
{
    extern __shared__ __align__(1024) uint8_t smraw[];
    const uint32_t sb = smem_u32(smraw);
    const int tid = threadIdx.x, lane = tid & 31, warp = tid >> 5;
    const int gid = lane >> 2, tg = lane & 3;
    const int wm = (warp >> 1) * 64;
    const int wn = (warp & 1) * 32;

    int cum[NEXP];
    {
        int acc = 0;
#pragma unroll
        for (int i = 0; i < NEXP; i++) { acc += __ldg(&counts[i]); cum[i] = acc; }
    }
    auto expert_of_row = [&](int row0) {
        int e = 0;
#pragma unroll
        for (int i = 0; i < NEXP - 1; i++) if (row0 >= cum[i]) e = i + 1;
        return e;
    };

    const int bid = blockIdx.x, gsz = gridDim.x;
    const int nmine = (GU_NT - bid + gsz - 1) / gsz;
    const int total = nmine * GU_NK;

    // 24 chunks per thread per iteration:
    //   i in [0,16): A  (kblk = i>>3, inner chunk = i&7)
    //   i in [16,20): G (kblk = (i-16)>>1, inner = (i-16)&1)
    //   i in [20,24): U (kblk = (i-20)>>1, inner = (i-20)&1)
    auto issue_chunk = [&](int it, int i) {
        if (it >= total) return;
        const int j = it >> 4, kt = it & (GU_NK - 1);
        const int tile = bid + j * gsz;
        const int row0 = (tile >> 4) * 256;
        const int n0   = (tile & 15) * 64;
        const int e = expert_of_row(row0);
        const int k0 = kt * 128;
        const uint32_t St = sb + (it & 1) * GU_STAGE_B;
        if (i < 16) {
            const int kblk = i >> 3;
            int c = tid + (i & 7) * 256; int r = c >> 3; int ch = c & 7;
            const __half* Ap = g_x16 + (size_t)row0 * DIM + k0 + kblk * 64;
            cpa16(tile_addr(St + kblk * 32768, r, ch), Ap + (size_t)r * DIM + ch * 8);
        } else if (i < 20) {
            const int kblk = (i - 16) >> 1;
            int c = tid + ((i - 16) & 1) * 256; int r = c >> 3; int ch = c & 7;
            const __half* Gp = g_g16 + (size_t)e * HID * DIM + (size_t)n0 * DIM + k0 + kblk * 64;
            cpa16(tile_addr(St + 65536 + kblk * 8192, r, ch), Gp + (size_t)r * DIM + ch * 8);
        } else {
            const int kblk = (i - 20) >> 1;
            int c = tid + ((i - 20) & 1) * 256; int r = c >> 3; int ch = c & 7;
            const __half* Up = g_u16 + (size_t)e * HID * DIM + (size_t)n0 * DIM + k0 + kblk * 64;
            cpa16(tile_addr(St + 81920 + kblk * 8192, r, ch), Up + (size_t)r * DIM + ch * 8);
        }
    };

    // prologue: fill stage 0
#pragma unroll
    for (int i = 0; i < 24; i++) issue_chunk(0, i);
    CP_COMMIT();

    float accg[4][4][4];
    float accu[4][4][4];

    const int a_row = lane & 15, a_ch = lane >> 4;
    const int b_row = (lane & 7) + ((lane & 16) >> 1), b_ch = (lane >> 3) & 1;

    for (int it = 0; it < total; it++) {
        const int kt = it & (GU_NK - 1);
        CP_WAIT0();                 // this thread's stage `it` (and all prior) complete
        __syncthreads();            // collective: all threads' stage `it` complete

        if (kt == 0) {
#pragma unroll
            for (int mi = 0; mi < 4; mi++)
#pragma unroll
                for (int ni = 0; ni < 4; ni++)
#pragma unroll
                    for (int q = 0; q < 4; q++) { accg[mi][ni][q] = 0.f; accu[mi][ni][q] = 0.f; }
        }

        const uint32_t St = sb + (it & 1) * GU_STAGE_B;
#pragma unroll
        for (int q = 0; q < 8; q++) {
            const int kblk = q >> 2, qq = q & 3;
            const uint32_t Ab = St + kblk * 32768;
            const uint32_t Gb = St + 65536 + kblk * 8192;
            const uint32_t Ub = St + 81920 + kblk * 8192;
            uint32_t af[4][4];
#pragma unroll
            for (int mi = 0; mi < 4; mi++)
                ldsm4(af[mi], tile_addr(Ab, wm + mi * 16 + a_row, 2 * qq + a_ch));
            uint32_t bg[4][2], bu[4][2];
#pragma unroll
            for (int nj = 0; nj < 2; nj++) {
                uint32_t t4[4];
                ldsm4(t4, tile_addr(Gb, wn + nj * 16 + b_row, 2 * qq + b_ch));
                bg[2 * nj][0] = t4[0]; bg[2 * nj][1] = t4[1];
                bg[2 * nj + 1][0] = t4[2]; bg[2 * nj + 1][1] = t4[3];
                ldsm4(t4, tile_addr(Ub, wn + nj * 16 + b_row, 2 * qq + b_ch));
                bu[2 * nj][0] = t4[0]; bu[2 * nj][1] = t4[1];
                bu[2 * nj + 1][0] = t4[2]; bu[2 * nj + 1][1] = t4[3];
            }
            // spread next-stage loads (3 per q-step, 24 total)
#pragma unroll
            for (int i = 3 * q; i < 3 * q + 3; i++) issue_chunk(it + 1, i);
#pragma unroll
            for (int ni = 0; ni < 4; ni++)
#pragma unroll
                for (int mi = 0; mi < 4; mi++) {
                    mma16816(accg[mi][ni], af[mi], bg[ni]);
                    mma16816(accu[mi][ni], af[mi], bu[ni]);
                }
        }
        CP_COMMIT();                // one commit per iteration

        if (kt == GU_NK - 1) {
            const int tile = bid + (it >> 4) * gsz;
            const int row0 = (tile >> 4) * 256;
            const int n0   = (tile & 15) * 64;
#pragma unroll
            for (int mi = 0; mi < 4; mi++)
#pragma unroll
                for (int ni = 0; ni < 4; ni++) {
                    int r = row0 + wm + mi * 16 + gid;
                    int c = n0 + wn + ni * 8 + tg * 2;
                    float g0 = accg[mi][ni][0], u0 = accu[mi][ni][0];
                    float g1 = accg[mi][ni][1], u1 = accu[mi][ni][1];
                    float g2 = accg[mi][ni][2], u2 = accu[mi][ni][2];
                    float g3 = accg[mi][ni][3], u3 = accu[mi][ni][3];
                    float h0 = g0 * u0 / (1.0f + __expf(-g0));
                    float h1 = g1 * u1 / (1.0f + __expf(-g1));
                    float h2 = g2 * u2 / (1.0f + __expf(-g2));
                    float h3 = g3 * u3 / (1.0f + __expf(-g3));
                    *reinterpret_cast<__half2*>(&g_h16[(size_t)r * HID + c]) =
                        __float22half2_rn(make_float2(h0, h1));
                    *reinterpret_cast<__half2*>(&g_h16[(size_t)(r + 8) * HID + c]) =
                        __float22half2_rn(make_float2(h2, h3));
                }
        }
    }
}

// ---------------------------------------------------------------------------
// Kernel 2: down, persistent. CTA tile BM=128 x BN=256, BK=128.
// 8 warps (2M x 4N), warp tile 64x64. Tiles: 8 x 128 = 1024, NK=8.
// 2 stages x 96K = 192K smem. Same double-buffer structure.
// Stage layout: A[2 kblk x 128r x 128B]=32K, B[2 x 256 x 128B]=64K.
// ---------------------------------------------------------------------------
#define DN_STAGE_B 98304
#define DN_NT 1024
#define DN_NK 8
__global__ __launch_bounds__(256, 1) void down_kernel(const int* __restrict__ counts,
                                                      float* __restrict__ out)
{
    extern __shared__ __align__(1024) uint8_t smraw[];
    const uint32_t sb = smem_u32(smraw);
    const int tid = threadIdx.x, lane = tid & 31, warp = tid >> 5;
    const int gid = lane >> 2, tg = lane & 3;
    const int wm = (warp >> 2) * 64;
    const int wn = (warp & 3) * 64;

    int cum[NEXP];
    {
        int acc = 0;
#pragma unroll
        for (int i = 0; i < NEXP; i++) { acc += __ldg(&counts[i]); cum[i] = acc; }
    }
    auto expert_of_row = [&](int row0) {
        int e = 0;
#pragma unroll
        for (int i = 0; i < NEXP - 1; i++) if (row0 >= cum[i]) e = i + 1;
        return e;
    };

    const int bid = blockIdx.x, gsz = gridDim.x;
    const int nmine = (DN_NT - bid + gsz - 1) / gsz;
    const int total = nmine * DN_NK;

    // 24 chunks: i in [0,8): A (kblk=i>>2, inner=i&3); i in [8,24): B (kblk=(i-8)>>3, inner=(i-8)&7)
    auto issue_chunk = [&](int it, int i) {
        if (it >= total) return;
        const int j = it >> 3, kt = it & (DN_NK - 1);
        const int tile = bid + j * gsz;
        const int row0 = (tile >> 3) * 128;
        const int n0   = (tile & 7) * 256;
        const int e = expert_of_row(row0);
        const int k0 = kt * 128;
        const uint32_t St = sb + (it & 1) * DN_STAGE_B;
        if (i < 8) {
            const int kblk = i >> 2;
            int c = tid + (i & 3) * 256; int r = c >> 3; int ch = c & 7;
            const __half* Ap = g_h16 + (size_t)row0 * HID + k0 + kblk * 64;
            cpa16(tile_addr(St + kblk * 16384, r, ch), Ap + (size_t)r * HID + ch * 8);
        } else {
            const int kblk = (i - 8) >> 3;
            int c = tid + ((i - 8) & 7) * 256; int r = c >> 3; int ch = c & 7;
            const __half* Bp = g_d16 + (size_t)e * DIM * HID + (size_t)n0 * HID + k0 + kblk * 64;
            cpa16(tile_addr(St + 32768 + kblk * 32768, r, ch), Bp + (size_t)r * HID + ch * 8);
        }
    };

#pragma unroll
    for (int i = 0; i < 24; i++) issue_chunk(0, i);
    CP_COMMIT();

    float acc[4][8][4];

    const int a_row = lane & 15, a_ch = lane >> 4;
    const int b_row = (lane & 7) + ((lane & 16) >> 1), b_ch = (lane >> 3) & 1;

    for (int it = 0; it < total; it++) {
        const int kt = it & (DN_NK - 1);
        CP_WAIT0();
        __syncthreads();

        if (kt == 0) {
#pragma unroll
            for (int mi = 0; mi < 4; mi++)
#pragma unroll
                for (int ni = 0; ni < 8; ni++)
#pragma unroll
                    for (int q = 0; q < 4; q++) acc[mi][ni][q] = 0.f;
        }

        const uint32_t St = sb + (it & 1) * DN_STAGE_B;
#pragma unroll
        for (int q = 0; q < 8; q++) {
            const int kblk = q >> 2, qq = q & 3;
            const uint32_t Ab = St + kblk * 16384;
            const uint32_t Bb = St + 32768 + kblk * 32768;
            uint32_t af[4][4];
#pragma unroll
            for (int mi = 0; mi < 4; mi++)
                ldsm4(af[mi], tile_addr(Ab, wm + mi * 16 + a_row, 2 * qq + a_ch));
            uint32_t bf[8][2];
#pragma unroll
            for (int nj = 0; nj < 4; nj++) {
                uint32_t t4[4];
                ldsm4(t4, tile_addr(Bb, wn + nj * 16 + b_row, 2 * qq + b_ch));
                bf[2 * nj][0] = t4[0]; bf[2 * nj][1] = t4[1];
                bf[2 * nj + 1][0] = t4[2]; bf[2 * nj + 1][1] = t4[3];
            }
#pragma unroll
            for (int i = 3 * q; i < 3 * q + 3; i++) issue_chunk(it + 1, i);
#pragma unroll
            for (int ni = 0; ni < 8; ni++)
#pragma unroll
                for (int mi = 0; mi < 4; mi++)
                    mma16816(acc[mi][ni], af[mi], bf[ni]);
        }
        CP_COMMIT();

        if (kt == DN_NK - 1) {
            const int tile = bid + (it >> 3) * gsz;
            const int row0 = (tile >> 3) * 128;
            const int n0   = (tile & 7) * 256;
#pragma unroll
            for (int mi = 0; mi < 4; mi++)
#pragma unroll
                for (int ni = 0; ni < 8; ni++) {
                    int r = row0 + wm + mi * 16 + gid;
                    int c = n0 + wn + ni * 8 + tg * 2;
                    *reinterpret_cast<float2*>(&out[(size_t)r * DIM + c]) =
                        make_float2(acc[mi][ni][0], acc[mi][ni][1]);
                    *reinterpret_cast<float2*>(&out[(size_t)(r + 8) * DIM + c]) =
                        make_float2(acc[mi][ni][2], acc[mi][ni][3]);
                }
        }
    }
}

extern "C" void kernel_launch(void* const* d_in, const int* in_sizes, int n_in,
                              void* d_out, int out_size) {
    const float* x      = (const float*)d_in[0];
    const float* gate   = (const float*)d_in[1];
    const float* up     = (const float*)d_in[2];
    const float* down   = (const float*)d_in[3];
    const int*   counts = (const int*)d_in[4];
    float* out = (float*)d_out;

    static bool attr_set = false;
    if (!attr_set) {
        cudaFuncSetAttribute(gateup_kernel, cudaFuncAttributeMaxDynamicSharedMemorySize,
                             2 * GU_STAGE_B);
        cudaFuncSetAttribute(down_kernel, cudaFuncAttributeMaxDynamicSharedMemorySize,
                             2 * DN_STAGE_B);
        attr_set = true;
    }

    __half* pd; cudaGetSymbolAddress((void**)&pd, g_d16);

    cvt3_kernel<<<1216, 256>>>(x, gate, up);
    gateup_kernel<<<152, 256, 2 * GU_STAGE_B>>>(counts);

    cvt_kernel<<<1216, 256>>>(down, pd, NW8);
    down_kernel<<<152, 256, 2 * DN_STAGE_B>>>(counts, out);
}

// round 14
// speedup vs baseline: 1.0007x; 1.0007x over previous
#include <cuda_runtime.h>
#include <cuda_fp16.h>
#include <cstdint>

#define DIM 2048
#define HID 1024
#define NEXP 8
#define TOTAL 16384
#define STAGES 4

// fp16 copies of inputs (converted once per launch) + fp16 h buffer
__device__ __half g_x16[(size_t)TOTAL * DIM];
__device__ __half g_g16[(size_t)NEXP * HID * DIM];
__device__ __half g_u16[(size_t)NEXP * HID * DIM];
__device__ __half g_d16[(size_t)NEXP * DIM * HID];
__device__ __half g_h16[(size_t)TOTAL * HID];

__device__ __forceinline__ uint32_t smem_u32(const void* p) {
    uint32_t a;
    asm("{ .reg .u64 t; cvta.to.shared.u64 t, %1; cvt.u32.u64 %0, t; }" : "=r"(a) : "l"(p));
    return a;
}
__device__ __forceinline__ void ldsm4(uint32_t r[4], uint32_t addr) {
    asm volatile("ldmatrix.sync.aligned.m8n8.x4.shared.b16 {%0,%1,%2,%3}, [%4];"
                 : "=r"(r[0]), "=r"(r[1]), "=r"(r[2]), "=r"(r[3]) : "r"(addr));
}
__device__ __forceinline__ void mma16816(float c[4], const uint32_t a[4], const uint32_t b[2]) {
    asm volatile(
        "mma.sync.aligned.m16n8k16.row.col.f32.f16.f16.f32 "
        "{%0,%1,%2,%3}, {%4,%5,%6,%7}, {%8,%9}, {%0,%1,%2,%3};"
        : "+f"(c[0]), "+f"(c[1]), "+f"(c[2]), "+f"(c[3])
        : "r"(a[0]), "r"(a[1]), "r"(a[2]), "r"(a[3]), "r"(b[0]), "r"(b[1]));
}
__device__ __forceinline__ void cpa16(uint32_t dst, const void* src) {
    asm volatile("cp.async.cg.shared.global [%0], [%1], 16;" :: "r"(dst), "l"(src) : "memory");
}
#define CP_COMMIT() asm volatile("cp.async.commit_group;" ::: "memory")
#define CP_WAIT2()  asm volatile("cp.async.wait_group 2;" ::: "memory")

// Tile rows are 128 bytes (64 fp16); chunk = 16B unit, XOR-8 swizzle (verified R6/R7).
__device__ __forceinline__ uint32_t tile_addr(uint32_t base, int row, int chunk) {
    return base + row * 128 + (((chunk ^ (row & 7)) & 7) << 4);
}

__device__ __forceinline__ void cvt8(const float* __restrict__ s, __half* __restrict__ d, size_t i) {
    const float4* sp = reinterpret_cast<const float4*>(s) + i * 2;
    float4 a = __ldcs(sp);
    float4 b = __ldcs(sp + 1);
    __half2 h0 = __float22half2_rn(make_float2(a.x, a.y));
    __half2 h1 = __float22half2_rn(make_float2(a.z, a.w));
    __half2 h2 = __float22half2_rn(make_float2(b.x, b.y));
    __half2 h3 = __float22half2_rn(make_float2(b.z, b.w));
    uint4 o = make_uint4(*reinterpret_cast<uint32_t*>(&h0), *reinterpret_cast<uint32_t*>(&h1),
                         *reinterpret_cast<uint32_t*>(&h2), *reinterpret_cast<uint32_t*>(&h3));
    reinterpret_cast<uint4*>(d)[i] = o;
}

// ---------------------------------------------------------------------------
// Merged convert for x, gate, up (one launch)
// ---------------------------------------------------------------------------
#define NX8 ((size_t)TOTAL * DIM / 8)
#define NW8 ((size_t)NEXP * HID * DIM / 8)
__global__ __launch_bounds__(256) void cvt3_kernel(const float* __restrict__ x,
                                                   const float* __restrict__ g,
                                                   const float* __restrict__ u)
{
    const size_t n = NX8 + 2 * NW8;
    size_t idx = (size_t)blockIdx.x * blockDim.x + threadIdx.x;
    size_t stride = (size_t)gridDim.x * blockDim.x;
    for (size_t i = idx; i < n; i += stride) {
        if (i < NX8)            cvt8(x, g_x16, i);
        else if (i < NX8 + NW8) cvt8(g, g_g16, i - NX8);
        else                    cvt8(u, g_u16, i - NX8 - NW8);
    }
}

// ---------------------------------------------------------------------------
// Kernel 1: gateup, persistent. CTA tile BM=256 x (64 gate + 64 up), BK=64.
// 8 warps (4M x 2N), warp tile 64x32 per matrix. Tiles: 16 x 64 = 1024, NK=32.
// Stage 48K x 4 = 192K smem. WAIT -> SYNC -> (spread issue) -> COMMIT (R12).
// TAIL FUSION: after its GEMM tiles, each CTA converts a slice of the down
// weights (fp32->fp16). CTAs with fewer tiles (6 vs 7) get a 2x slice, so the
// conversion fills the persistent-tail idle window. Stream order guarantees
// g_d16 is complete before down_kernel launches.
// ---------------------------------------------------------------------------
#define GU_STAGE_B 49152
#define GU_NT 1024
#define GU_NK 32
__global__ __launch_bounds__(256, 1) void gateup_kernel(const int* __restrict__ counts,
                                                        const float* __restrict__ downw)
{
    extern __shared__ __align__(1024) uint8_t smraw[];
    const uint32_t sb = smem_u32(smraw);
    const int tid = threadIdx.x, lane = tid & 31, warp = tid >> 5;
    const int gid = lane >> 2, tg = lane & 3;
    const int wm = (warp >> 1) * 64;
    const int wn = (warp & 1) * 32;

    int cum[NEXP];
    {
        int acc = 0;
#pragma unroll
        for (int i = 0; i < NEXP; i++) { acc += __ldg(&counts[i]); cum[i] = acc; }
    }
    auto expert_of_row = [&](int row0) {
        int e = 0;
#pragma unroll
        for (int i = 0; i < NEXP - 1; i++) if (row0 >= cum[i]) e = i + 1;
        return e;
    };

    const int bid = blockIdx.x, gsz = gridDim.x;
    const int nmine = (GU_NT - bid + gsz - 1) / gsz;
    const int total = nmine * GU_NK;

    // chunk i of the 12 per-thread cp.asyncs for iteration `it` (i in 0..11):
    // i<8 -> A, i in {8,9} -> G, i in {10,11} -> U.
    auto issue_chunk = [&](int it, int i) {
        if (it >= total) return;
        const int j = it >> 5, kt = it & (GU_NK - 1);
        const int tile = bid + j * gsz;
        const int row0 = (tile >> 4) * 256;
        const int n0   = (tile & 15) * 64;
        const int e = expert_of_row(row0);
        const int s = it & (STAGES - 1);
        const uint32_t Ab = sb + s * GU_STAGE_B;
        if (i < 8) {
            int c = tid + i * 256; int r = c >> 3; int ch = c & 7;
            const __half* Ap = g_x16 + (size_t)row0 * DIM + kt * 64;
            cpa16(tile_addr(Ab, r, ch), Ap + (size_t)r * DIM + ch * 8);
        } else if (i < 10) {
            int c = tid + (i - 8) * 256; int r = c >> 3; int ch = c & 7;
            const __half* Gp = g_g16 + (size_t)e * HID * DIM + (size_t)n0 * DIM + kt * 64;
            cpa16(tile_addr(Ab + 32768, r, ch), Gp + (size_t)r * DIM + ch * 8);
        } else {
            int c = tid + (i - 10) * 256; int r = c >> 3; int ch = c & 7;
            const __half* Up = g_u16 + (size_t)e * HID * DIM + (size_t)n0 * DIM + kt * 64;
            cpa16(tile_addr(Ab + 40960, r, ch), Up + (size_t)r * DIM + ch * 8);
        }
    };
    auto issue_all = [&](int it) {
#pragma unroll
        for (int i = 0; i < 12; i++) issue_chunk(it, i);
        CP_COMMIT();
    };

    issue_all(0); issue_all(1); issue_all(2);

    float accg[4][4][4];
    float accu[4][4][4];

    const int a_row = lane & 15, a_ch = lane >> 4;
    const int b_row = (lane & 7) + ((lane & 16) >> 1), b_ch = (lane >> 3) & 1;

    for (int it = 0; it < total; it++) {
        const int kt = it & (GU_NK - 1);
        CP_WAIT2();                 // this thread's group `it` complete
        __syncthreads();            // ALL threads' group `it` complete; stage it-1 consumed

        if (kt == 0) {
#pragma unroll
            for (int mi = 0; mi < 4; mi++)
#pragma unroll
                for (int ni = 0; ni < 4; ni++)
#pragma unroll
                    for (int q = 0; q < 4; q++) { accg[mi][ni][q] = 0.f; accu[mi][ni][q] = 0.f; }
        }

        const int s = it & (STAGES - 1);
        const uint32_t Ab = sb + s * GU_STAGE_B;
        const uint32_t Gb = Ab + 32768;
        const uint32_t Ub = Gb + 8192;
#pragma unroll
        for (int q = 0; q < 4; q++) {
            uint32_t af[4][4];
#pragma unroll
            for (int mi = 0; mi < 4; mi++)
                ldsm4(af[mi], tile_addr(Ab, wm + mi * 16 + a_row, 2 * q + a_ch));
            uint32_t bg[4][2], bu[4][2];
#pragma unroll
            for (int nj = 0; nj < 2; nj++) {
                uint32_t t4[4];
                ldsm4(t4, tile_addr(Gb, wn + nj * 16 + b_row, 2 * q + b_ch));
                bg[2 * nj][0] = t4[0]; bg[2 * nj][1] = t4[1];
                bg[2 * nj + 1][0] = t4[2]; bg[2 * nj + 1][1] = t4[3];
                ldsm4(t4, tile_addr(Ub, wn + nj * 16 + b_row, 2 * q + b_ch));
                bu[2 * nj][0] = t4[0]; bu[2 * nj][1] = t4[1];
                bu[2 * nj + 1][0] = t4[2]; bu[2 * nj + 1][1] = t4[3];
            }
            // spread next-stage loads under the MMA shadow (3 per q-step)
#pragma unroll
            for (int i = 3 * q; i < 3 * q + 3; i++) issue_chunk(it + STAGES - 1, i);
#pragma unroll
            for (int ni = 0; ni < 4; ni++)
#pragma unroll
                for (int mi = 0; mi < 4; mi++) {
                    mma16816(accg[mi][ni], af[mi], bg[ni]);
                    mma16816(accu[mi][ni], af[mi], bu[ni]);
                }
        }
        CP_COMMIT();                // one commit per iteration (tail-safe, uniform)

        if (kt == GU_NK - 1) {
            const int tile = bid + (it >> 5) * gsz;
            const int row0 = (tile >> 4) * 256;
            const int n0   = (tile & 15) * 64;
#pragma unroll
            for (int mi = 0; mi < 4; mi++)
#pragma unroll
                for (int ni = 0; ni < 4; ni++) {
                    int r = row0 + wm + mi * 16 + gid;
                    int c = n0 + wn + ni * 8 + tg * 2;
                    float g0 = accg[mi][ni][0], u0 = accu[mi][ni][0];
                    float g1 = accg[mi][ni][1], u1 = accu[mi][ni][1];
                    float g2 = accg[mi][ni][2], u2 = accu[mi][ni][2];
                    float g3 = accg[mi][ni][3], u3 = accu[mi][ni][3];
                    float h0 = g0 * u0 / (1.0f + __expf(-g0));
                    float h1 = g1 * u1 / (1.0f + __expf(-g1));
                    float h2 = g2 * u2 / (1.0f + __expf(-g2));
                    float h3 = g3 * u3 / (1.0f + __expf(-g3));
                    *reinterpret_cast<__half2*>(&g_h16[(size_t)r * HID + c]) =
                        __float22half2_rn(make_float2(h0, h1));
                    *reinterpret_cast<__half2*>(&g_h16[(size_t)(r + 8) * HID + c]) =
                        __float22half2_rn(make_float2(h2, h3));
                }
        }
    }

    // ---- tail fusion: convert down weights (fp32 -> fp16) ----
    // 1024 = 152*6 + 112 -> bids [0,112) own 7 tiles (weight 1),
    // bids [112,152) own 6 tiles (weight 2). Weighted prefix splits NW8.
    {
        const int w      = (bid < 112) ? 1 : 2;
        const int prefix = (bid < 112) ? bid : 112 + 2 * (bid - 112);
        const int totw   = 112 + 2 * (gsz - 112);          // 192 for gsz=152
        const size_t unit = (NW8 + totw - 1) / totw;
        size_t start = (size_t)prefix * unit;
        size_t end   = start + (size_t)w * unit;
        if (end > NW8) end = NW8;
        for (size_t i = start + tid; i < end; i += 256)
            cvt8(downw, g_d16, i);
    }
}

// ---------------------------------------------------------------------------
// Kernel 2: down, persistent. CTA tile BM=128 x BN=256, BK=64.
// 8 warps (2M x 4N), warp tile 64x64. Tiles: 8 x 128 = 1024, NK=16.
// Stage 48K x 4 = 192K smem. R12 spread-issue structure (verified).
// ---------------------------------------------------------------------------
#define DN_STAGE_B 49152
#define DN_NT 1024
#define DN_NK 16
__global__ __launch_bounds__(256, 1) void down_kernel(const int* __restrict__ counts,
                                                      float* __restrict__ out)
{
    extern __shared__ __align__(1024) uint8_t smraw[];
    const uint32_t sb = smem_u32(smraw);
    const int tid = threadIdx.x, lane = tid & 31, warp = tid >> 5;
    const int gid = lane >> 2, tg = lane & 3;
    const int wm = (warp >> 2) * 64;
    const int wn = (warp & 3) * 64;

    int cum[NEXP];
    {
        int acc = 0;
#pragma unroll
        for (int i = 0; i < NEXP; i++) { acc += __ldg(&counts[i]); cum[i] = acc; }
    }
    auto expert_of_row = [&](int row0) {
        int e = 0;
#pragma unroll
        for (int i = 0; i < NEXP - 1; i++) if (row0 >= cum[i]) e = i + 1;
        return e;
    };

    const int bid = blockIdx.x, gsz = gridDim.x;
    const int nmine = (DN_NT - bid + gsz - 1) / gsz;
    const int total = nmine * DN_NK;

    // chunk i of 12: i<4 -> A, i>=4 -> B (chunk i-4 of 8)
    auto issue_chunk = [&](int it, int i) {
        if (it >= total) return;
        const int j = it >> 4, kt = it & (DN_NK - 1);
        const int tile = bid + j * gsz;
        const int row0 = (tile >> 3) * 128;
        const int n0   = (tile & 7) * 256;
        const int e = expert_of_row(row0);
        const int s = it & (STAGES - 1);
        const uint32_t Ab = sb + s * DN_STAGE_B;
        if (i < 4) {
            int c = tid + i * 256; int r = c >> 3; int ch = c & 7;
            const __half* Ap = g_h16 + (size_t)row0 * HID + kt * 64;
            cpa16(tile_addr(Ab, r, ch), Ap + (size_t)r * HID + ch * 8);
        } else {
            int c = tid + (i - 4) * 256; int r = c >> 3; int ch = c & 7;
            const __half* Bp = g_d16 + (size_t)e * DIM * HID + (size_t)n0 * HID + kt * 64;
            cpa16(tile_addr(Ab + 16384, r, ch), Bp + (size_t)r * HID + ch * 8);
        }
    };
    auto issue_all = [&](int it) {
#pragma unroll
        for (int i = 0; i < 12; i++) issue_chunk(it, i);
        CP_COMMIT();
    };

    issue_all(0); issue_all(1); issue_all(2);

    float acc[4][8][4];

    const int a_row = lane & 15, a_ch = lane >> 4;
    const int b_row = (lane & 7) + ((lane & 16) >> 1), b_ch = (lane >> 3) & 1;

    for (int it = 0; it < total; it++) {
        const int kt = it & (DN_NK - 1);
        CP_WAIT2();
        __syncthreads();

        if (kt == 0) {
#pragma unroll
            for (int mi = 0; mi < 4; mi++)
#pragma unroll
                for (int ni = 0; ni < 8; ni++)
#pragma unroll
                    for (int q = 0; q < 4; q++) acc[mi][ni][q] = 0.f;
        }

        const int s = it & (STAGES - 1);
        const uint32_t Ab = sb + s * DN_STAGE_B;
        const uint32_t Bb = Ab + 16384;
#pragma unroll
        for (int q = 0; q < 4; q++) {
            uint32_t af[4][4];
#pragma unroll
            for (int mi = 0; mi < 4; mi++)
                ldsm4(af[mi], tile_addr(Ab, wm + mi * 16 + a_row, 2 * q + a_ch));
            uint32_t bf[8][2];
#pragma unroll
            for (int nj = 0; nj < 4; nj++) {
                uint32_t t4[4];
                ldsm4(t4, tile_addr(Bb, wn + nj * 16 + b_row, 2 * q + b_ch));
                bf[2 * nj][0] = t4[0]; bf[2 * nj][1] = t4[1];
                bf[2 * nj + 1][0] = t4[2]; bf[2 * nj + 1][1] = t4[3];
            }
#pragma unroll
            for (int i = 3 * q; i < 3 * q + 3; i++) issue_chunk(it + STAGES - 1, i);
#pragma unroll
            for (int ni = 0; ni < 8; ni++)
#pragma unroll
                for (int mi = 0; mi < 4; mi++)
                    mma16816(acc[mi][ni], af[mi], bf[ni]);
        }
        CP_COMMIT();

        if (kt == DN_NK - 1) {
            const int tile = bid + (it >> 4) * gsz;
            const int row0 = (tile >> 3) * 128;
            const int n0   = (tile & 7) * 256;
#pragma unroll
            for (int mi = 0; mi < 4; mi++)
#pragma unroll
                for (int ni = 0; ni < 8; ni++) {
                    int r = row0 + wm + mi * 16 + gid;
                    int c = n0 + wn + ni * 8 + tg * 2;
                    *reinterpret_cast<float2*>(&out[(size_t)r * DIM + c]) =
                        make_float2(acc[mi][ni][0], acc[mi][ni][1]);
                    *reinterpret_cast<float2*>(&out[(size_t)(r + 8) * DIM + c]) =
                        make_float2(acc[mi][ni][2], acc[mi][ni][3]);
                }
        }
    }
}

extern "C" void kernel_launch(void* const* d_in, const int* in_sizes, int n_in,
                              void* d_out, int out_size) {
    const float* x      = (const float*)d_in[0];
    const float* gate   = (const float*)d_in[1];
    const float* up     = (const float*)d_in[2];
    const float* down   = (const float*)d_in[3];
    const int*   counts = (const int*)d_in[4];
    float* out = (float*)d_out;

    static bool attr_set = false;
    if (!attr_set) {
        cudaFuncSetAttribute(gateup_kernel, cudaFuncAttributeMaxDynamicSharedMemorySize,
                             STAGES * GU_STAGE_B);
        cudaFuncSetAttribute(down_kernel, cudaFuncAttributeMaxDynamicSharedMemorySize,
                             STAGES * DN_STAGE_B);
        attr_set = true;
    }

    // convert x, gate, up (one merged launch)
    cvt3_kernel<<<1216, 256>>>(x, gate, up);
    // gateup GEMM + fused down-weight conversion in the persistent tail
    gateup_kernel<<<152, 256, STAGES * GU_STAGE_B>>>(counts, down);
    down_kernel<<<152, 256, STAGES * DN_STAGE_B>>>(counts, out);
}

// round 15
// speedup vs baseline: 1.0261x; 1.0254x over previous
#include <cuda_runtime.h>
#include <cuda_fp16.h>
#include <cstdint>

#define DIM 2048
#define HID 1024
#define NEXP 8
#define TOTAL 16384
#define STAGES 4

// fp16 copies of inputs (converted once per launch) + fp16 h buffer
__device__ __half g_x16[(size_t)TOTAL * DIM];
__device__ __half g_g16[(size_t)NEXP * HID * DIM];
__device__ __half g_u16[(size_t)NEXP * HID * DIM];
__device__ __half g_d16[(size_t)NEXP * DIM * HID];
__device__ __half g_h16[(size_t)TOTAL * HID];

__device__ __forceinline__ uint32_t smem_u32(const void* p) {
    uint32_t a;
    asm("{ .reg .u64 t; cvta.to.shared.u64 t, %1; cvt.u32.u64 %0, t; }" : "=r"(a) : "l"(p));
    return a;
}
__device__ __forceinline__ void ldsm4(uint32_t r[4], uint32_t addr) {
    asm volatile("ldmatrix.sync.aligned.m8n8.x4.shared.b16 {%0,%1,%2,%3}, [%4];"
                 : "=r"(r[0]), "=r"(r[1]), "=r"(r[2]), "=r"(r[3]) : "r"(addr));
}
__device__ __forceinline__ void mma16816(float c[4], const uint32_t a[4], const uint32_t b[2]) {
    asm volatile(
        "mma.sync.aligned.m16n8k16.row.col.f32.f16.f16.f32 "
        "{%0,%1,%2,%3}, {%4,%5,%6,%7}, {%8,%9}, {%0,%1,%2,%3};"
        : "+f"(c[0]), "+f"(c[1]), "+f"(c[2]), "+f"(c[3])
        : "r"(a[0]), "r"(a[1]), "r"(a[2]), "r"(a[3]), "r"(b[0]), "r"(b[1]));
}
__device__ __forceinline__ void cpa16(uint32_t dst, const void* src) {
    asm volatile("cp.async.cg.shared.global [%0], [%1], 16;" :: "r"(dst), "l"(src) : "memory");
}
#define CP_COMMIT() asm volatile("cp.async.commit_group;" ::: "memory")
#define CP_WAIT2()  asm volatile("cp.async.wait_group 2;" ::: "memory")

// Tile rows are 128 bytes (64 fp16); chunk = 16B unit, XOR-8 swizzle (verified R6/R7).
__device__ __forceinline__ uint32_t tile_addr(uint32_t base, int row, int chunk) {
    return base + row * 128 + (((chunk ^ (row & 7)) & 7) << 4);
}

__device__ __forceinline__ void cvt8(const float* __restrict__ s, __half* __restrict__ d, size_t i) {
    const float4* sp = reinterpret_cast<const float4*>(s) + i * 2;
    float4 a = __ldcs(sp);
    float4 b = __ldcs(sp + 1);
    __half2 h0 = __float22half2_rn(make_float2(a.x, a.y));
    __half2 h1 = __float22half2_rn(make_float2(a.z, a.w));
    __half2 h2 = __float22half2_rn(make_float2(b.x, b.y));
    __half2 h3 = __float22half2_rn(make_float2(b.z, b.w));
    uint4 o = make_uint4(*reinterpret_cast<uint32_t*>(&h0), *reinterpret_cast<uint32_t*>(&h1),
                         *reinterpret_cast<uint32_t*>(&h2), *reinterpret_cast<uint32_t*>(&h3));
    reinterpret_cast<uint4*>(d)[i] = o;
}

// ---------------------------------------------------------------------------
// Merged convert for x, gate, up (one launch)
// ---------------------------------------------------------------------------
#define NX8 ((size_t)TOTAL * DIM / 8)
#define NW8 ((size_t)NEXP * HID * DIM / 8)
__global__ __launch_bounds__(256) void cvt3_kernel(const float* __restrict__ x,
                                                   const float* __restrict__ g,
                                                   const float* __restrict__ u)
{
    const size_t n = NX8 + 2 * NW8;
    size_t idx = (size_t)blockIdx.x * blockDim.x + threadIdx.x;
    size_t stride = (size_t)gridDim.x * blockDim.x;
    for (size_t i = idx; i < n; i += stride) {
        if (i < NX8)            cvt8(x, g_x16, i);
        else if (i < NX8 + NW8) cvt8(g, g_g16, i - NX8);
        else                    cvt8(u, g_u16, i - NX8 - NW8);
    }
}

__global__ __launch_bounds__(256) void cvt_kernel(const float* __restrict__ src,
                                                  __half* __restrict__ dst, size_t n8)
{
    size_t idx = (size_t)blockIdx.x * blockDim.x + threadIdx.x;
    size_t stride = (size_t)gridDim.x * blockDim.x;
    for (size_t i = idx; i < n8; i += stride) cvt8(src, dst, i);
}

// ---------------------------------------------------------------------------
// Kernel 1: gateup, persistent. CTA tile BM=256 x (64 gate + 64 up), BK=64.
// 8 warps (4M x 2N), warp tile 64x32 per matrix. Tiles: 16 x 64 = 1024, NK=32.
// Stage 48K x 4 = 192K smem. WAIT -> SYNC -> (spread issue) -> COMMIT (R12).
// ---------------------------------------------------------------------------
#define GU_STAGE_B 49152
#define GU_NT 1024
#define GU_NK 32
__global__ __launch_bounds__(256, 1) void gateup_kernel(const int* __restrict__ counts)
{
    extern __shared__ __align__(1024) uint8_t smraw[];
    const uint32_t sb = smem_u32(smraw);
    const int tid = threadIdx.x, lane = tid & 31, warp = tid >> 5;
    const int gid = lane >> 2, tg = lane & 3;
    const int wm = (warp >> 1) * 64;
    const int wn = (warp & 1) * 32;

    int cum[NEXP];
    {
        int acc = 0;
#pragma unroll
        for (int i = 0; i < NEXP; i++) { acc += __ldg(&counts[i]); cum[i] = acc; }
    }
    auto expert_of_row = [&](int row0) {
        int e = 0;
#pragma unroll
        for (int i = 0; i < NEXP - 1; i++) if (row0 >= cum[i]) e = i + 1;
        return e;
    };

    const int bid = blockIdx.x, gsz = gridDim.x;
    const int nmine = (GU_NT - bid + gsz - 1) / gsz;
    const int total = nmine * GU_NK;

    // chunk i of the 12 per-thread cp.asyncs for iteration `it` (i in 0..11):
    // i<8 -> A, i in {8,9} -> G, i in {10,11} -> U.
    auto issue_chunk = [&](int it, int i) {
        if (it >= total) return;
        const int j = it >> 5, kt = it & (GU_NK - 1);
        const int tile = bid + j * gsz;
        const int row0 = (tile >> 4) * 256;
        const int n0   = (tile & 15) * 64;
        const int e = expert_of_row(row0);
        const int s = it & (STAGES - 1);
        const uint32_t Ab = sb + s * GU_STAGE_B;
        if (i < 8) {
            int c = tid + i * 256; int r = c >> 3; int ch = c & 7;
            const __half* Ap = g_x16 + (size_t)row0 * DIM + kt * 64;
            cpa16(tile_addr(Ab, r, ch), Ap + (size_t)r * DIM + ch * 8);
        } else if (i < 10) {
            int c = tid + (i - 8) * 256; int r = c >> 3; int ch = c & 7;
            const __half* Gp = g_g16 + (size_t)e * HID * DIM + (size_t)n0 * DIM + kt * 64;
            cpa16(tile_addr(Ab + 32768, r, ch), Gp + (size_t)r * DIM + ch * 8);
        } else {
            int c = tid + (i - 10) * 256; int r = c >> 3; int ch = c & 7;
            const __half* Up = g_u16 + (size_t)e * HID * DIM + (size_t)n0 * DIM + kt * 64;
            cpa16(tile_addr(Ab + 40960, r, ch), Up + (size_t)r * DIM + ch * 8);
        }
    };
    auto issue_all = [&](int it) {
#pragma unroll
        for (int i = 0; i < 12; i++) issue_chunk(it, i);
        CP_COMMIT();
    };

    issue_all(0); issue_all(1); issue_all(2);

    float accg[4][4][4];
    float accu[4][4][4];

    const int a_row = lane & 15, a_ch = lane >> 4;
    const int b_row = (lane & 7) + ((lane & 16) >> 1), b_ch = (lane >> 3) & 1;

    for (int it = 0; it < total; it++) {
        const int kt = it & (GU_NK - 1);
        CP_WAIT2();                 // this thread's group `it` complete
        __syncthreads();            // ALL threads' group `it` complete; stage it-1 consumed

        if (kt == 0) {
#pragma unroll
            for (int mi = 0; mi < 4; mi++)
#pragma unroll
                for (int ni = 0; ni < 4; ni++)
#pragma unroll
                    for (int q = 0; q < 4; q++) { accg[mi][ni][q] = 0.f; accu[mi][ni][q] = 0.f; }
        }

        const int s = it & (STAGES - 1);
        const uint32_t Ab = sb + s * GU_STAGE_B;
        const uint32_t Gb = Ab + 32768;
        const uint32_t Ub = Gb + 8192;
#pragma unroll
        for (int q = 0; q < 4; q++) {
            uint32_t af[4][4];
#pragma unroll
            for (int mi = 0; mi < 4; mi++)
                ldsm4(af[mi], tile_addr(Ab, wm + mi * 16 + a_row, 2 * q + a_ch));
            uint32_t bg[4][2], bu[4][2];
#pragma unroll
            for (int nj = 0; nj < 2; nj++) {
                uint32_t t4[4];
                ldsm4(t4, tile_addr(Gb, wn + nj * 16 + b_row, 2 * q + b_ch));
                bg[2 * nj][0] = t4[0]; bg[2 * nj][1] = t4[1];
                bg[2 * nj + 1][0] = t4[2]; bg[2 * nj + 1][1] = t4[3];
                ldsm4(t4, tile_addr(Ub, wn + nj * 16 + b_row, 2 * q + b_ch));
                bu[2 * nj][0] = t4[0]; bu[2 * nj][1] = t4[1];
                bu[2 * nj + 1][0] = t4[2]; bu[2 * nj + 1][1] = t4[3];
            }
            // spread next-stage loads under the MMA shadow (3 per q-step)
#pragma unroll
            for (int i = 3 * q; i < 3 * q + 3; i++) issue_chunk(it + STAGES - 1, i);
#pragma unroll
            for (int ni = 0; ni < 4; ni++)
#pragma unroll
                for (int mi = 0; mi < 4; mi++) {
                    mma16816(accg[mi][ni], af[mi], bg[ni]);
                    mma16816(accu[mi][ni], af[mi], bu[ni]);
                }
        }
        CP_COMMIT();                // one commit per iteration (tail-safe, uniform)

        if (kt == GU_NK - 1) {
            const int tile = bid + (it >> 5) * gsz;
            const int row0 = (tile >> 4) * 256;
            const int n0   = (tile & 15) * 64;
#pragma unroll
            for (int mi = 0; mi < 4; mi++)
#pragma unroll
                for (int ni = 0; ni < 4; ni++) {
                    int r = row0 + wm + mi * 16 + gid;
                    int c = n0 + wn + ni * 8 + tg * 2;
                    float g0 = accg[mi][ni][0], u0 = accu[mi][ni][0];
                    float g1 = accg[mi][ni][1], u1 = accu[mi][ni][1];
                    float g2 = accg[mi][ni][2], u2 = accu[mi][ni][2];
                    float g3 = accg[mi][ni][3], u3 = accu[mi][ni][3];
                    float h0 = g0 * u0 / (1.0f + __expf(-g0));
                    float h1 = g1 * u1 / (1.0f + __expf(-g1));
                    float h2 = g2 * u2 / (1.0f + __expf(-g2));
                    float h3 = g3 * u3 / (1.0f + __expf(-g3));
                    *reinterpret_cast<__half2*>(&g_h16[(size_t)r * HID + c]) =
                        __float22half2_rn(make_float2(h0, h1));
                    *reinterpret_cast<__half2*>(&g_h16[(size_t)(r + 8) * HID + c]) =
                        __float22half2_rn(make_float2(h2, h3));
                }
        }
    }
}

// ---------------------------------------------------------------------------
// Kernel 2: down, persistent. CTA tile BM=128 x BN=256, BK=64.
// 8 warps (2M x 4N), warp tile 64x64. Tiles: 8 x 128 = 1024, NK=16.
// Stage 48K x 4 = 192K smem. R12 spread-issue structure (verified).
// ---------------------------------------------------------------------------
#define DN_STAGE_B 49152
#define DN_NT 1024
#define DN_NK 16
__global__ __launch_bounds__(256, 1) void down_kernel(const int* __restrict__ counts,
                                                      float* __restrict__ out)
{
    extern __shared__ __align__(1024) uint8_t smraw[];
    const uint32_t sb = smem_u32(smraw);
    const int tid = threadIdx.x, lane = tid & 31, warp = tid >> 5;
    const int gid = lane >> 2, tg = lane & 3;
    const int wm = (warp >> 2) * 64;
    const int wn = (warp & 3) * 64;

    int cum[NEXP];
    {
        int acc = 0;
#pragma unroll
        for (int i = 0; i < NEXP; i++) { acc += __ldg(&counts[i]); cum[i] = acc; }
    }
    auto expert_of_row = [&](int row0) {
        int e = 0;
#pragma unroll
        for (int i = 0; i < NEXP - 1; i++) if (row0 >= cum[i]) e = i + 1;
        return e;
    };

    const int bid = blockIdx.x, gsz = gridDim.x;
    const int nmine = (DN_NT - bid + gsz - 1) / gsz;
    const int total = nmine * DN_NK;

    // chunk i of 12: i<4 -> A, i>=4 -> B (chunk i-4 of 8)
    auto issue_chunk = [&](int it, int i) {
        if (it >= total) return;
        const int j = it >> 4, kt = it & (DN_NK - 1);
        const int tile = bid + j * gsz;
        const int row0 = (tile >> 3) * 128;
        const int n0   = (tile & 7) * 256;
        const int e = expert_of_row(row0);
        const int s = it & (STAGES - 1);
        const uint32_t Ab = sb + s * DN_STAGE_B;
        if (i < 4) {
            int c = tid + i * 256; int r = c >> 3; int ch = c & 7;
            const __half* Ap = g_h16 + (size_t)row0 * HID + kt * 64;
            cpa16(tile_addr(Ab, r, ch), Ap + (size_t)r * HID + ch * 8);
        } else {
            int c = tid + (i - 4) * 256; int r = c >> 3; int ch = c & 7;
            const __half* Bp = g_d16 + (size_t)e * DIM * HID + (size_t)n0 * HID + kt * 64;
            cpa16(tile_addr(Ab + 16384, r, ch), Bp + (size_t)r * HID + ch * 8);
        }
    };
    auto issue_all = [&](int it) {
#pragma unroll
        for (int i = 0; i < 12; i++) issue_chunk(it, i);
        CP_COMMIT();
    };

    issue_all(0); issue_all(1); issue_all(2);

    float acc[4][8][4];

    const int a_row = lane & 15, a_ch = lane >> 4;
    const int b_row = (lane & 7) + ((lane & 16) >> 1), b_ch = (lane >> 3) & 1;

    for (int it = 0; it < total; it++) {
        const int kt = it & (DN_NK - 1);
        CP_WAIT2();
        __syncthreads();

        if (kt == 0) {
#pragma unroll
            for (int mi = 0; mi < 4; mi++)
#pragma unroll
                for (int ni = 0; ni < 8; ni++)
#pragma unroll
                    for (int q = 0; q < 4; q++) acc[mi][ni][q] = 0.f;
        }

        const int s = it & (STAGES - 1);
        const uint32_t Ab = sb + s * DN_STAGE_B;
        const uint32_t Bb = Ab + 16384;
#pragma unroll
        for (int q = 0; q < 4; q++) {
            uint32_t af[4][4];
#pragma unroll
            for (int mi = 0; mi < 4; mi++)
                ldsm4(af[mi], tile_addr(Ab, wm + mi * 16 + a_row, 2 * q + a_ch));
            uint32_t bf[8][2];
#pragma unroll
            for (int nj = 0; nj < 4; nj++) {
                uint32_t t4[4];
                ldsm4(t4, tile_addr(Bb, wn + nj * 16 + b_row, 2 * q + b_ch));
                bf[2 * nj][0] = t4[0]; bf[2 * nj][1] = t4[1];
                bf[2 * nj + 1][0] = t4[2]; bf[2 * nj + 1][1] = t4[3];
            }
#pragma unroll
            for (int i = 3 * q; i < 3 * q + 3; i++) issue_chunk(it + STAGES - 1, i);
#pragma unroll
            for (int ni = 0; ni < 8; ni++)
#pragma unroll
                for (int mi = 0; mi < 4; mi++)
                    mma16816(acc[mi][ni], af[mi], bf[ni]);
        }
        CP_COMMIT();

        if (kt == DN_NK - 1) {
            const int tile = bid + (it >> 4) * gsz;
            const int row0 = (tile >> 3) * 128;
            const int n0   = (tile & 7) * 256;
#pragma unroll
            for (int mi = 0; mi < 4; mi++)
#pragma unroll
                for (int ni = 0; ni < 8; ni++) {
                    int r = row0 + wm + mi * 16 + gid;
                    int c = n0 + wn + ni * 8 + tg * 2;
                    *reinterpret_cast<float2*>(&out[(size_t)r * DIM + c]) =
                        make_float2(acc[mi][ni][0], acc[mi][ni][1]);
                    *reinterpret_cast<float2*>(&out[(size_t)(r + 8) * DIM + c]) =
                        make_float2(acc[mi][ni][2], acc[mi][ni][3]);
                }
        }
    }
}

extern "C" void kernel_launch(void* const* d_in, const int* in_sizes, int n_in,
                              void* d_out, int out_size) {
    const float* x      = (const float*)d_in[0];
    const float* gate   = (const float*)d_in[1];
    const float* up     = (const float*)d_in[2];
    const float* down   = (const float*)d_in[3];
    const int*   counts = (const int*)d_in[4];
    float* out = (float*)d_out;

    static bool init_done = false;
    static cudaStream_t s2;
    static cudaEvent_t ev_fork, ev_join;
    if (!init_done) {
        cudaFuncSetAttribute(gateup_kernel, cudaFuncAttributeMaxDynamicSharedMemorySize,
                             STAGES * GU_STAGE_B);
        cudaFuncSetAttribute(down_kernel, cudaFuncAttributeMaxDynamicSharedMemorySize,
                             STAGES * DN_STAGE_B);
        cudaStreamCreateWithFlags(&s2, cudaStreamNonBlocking);
        cudaEventCreateWithFlags(&ev_fork, cudaEventDisableTiming);
        cudaEventCreateWithFlags(&ev_join, cudaEventDisableTiming);
        init_done = true;
    }

    __half* pd; cudaGetSymbolAddress((void**)&pd, g_d16);

    // convert x, gate, up on the main stream
    cvt3_kernel<<<1216, 256>>>(x, gate, up);

    // fork: cvt_down runs on side stream, overlapping gateup (fills its
    // SM-retirement tail; worst case runs right after gateup, same as serial)
    cudaEventRecord(ev_fork, 0);
    cudaStreamWaitEvent(s2, ev_fork, 0);
    cvt_kernel<<<1216, 256, 0, s2>>>(down, pd, NW8);
    cudaEventRecord(ev_join, s2);

    gateup_kernel<<<152, 256, STAGES * GU_STAGE_B>>>(counts);

    // join: down_kernel needs both gateup (h) and cvt_down (g_d16)
    cudaStreamWaitEvent(0, ev_join, 0);
    down_kernel<<<152, 256, STAGES * DN_STAGE_B>>>(counts, out);
}